// round 11
// baseline (speedup 1.0000x reference)
#include <cuda_runtime.h>
#include <cstdint>
#include <cstddef>

constexpr int T  = 16;   // timesteps (innermost, contiguous)
constexpr int NB = 128;  // batch

// ---------------- static scratch (allocation-free) ----------------
__device__ float g_h1[NB*32*28*28*T];   // 205 MB
__device__ float g_h2[NB*32*28*28*T];
__device__ float g_h3[NB*32*28*28*T];
__device__ float g_h4[NB*32*14*14*T];
__device__ float g_h5[NB*16*14*14*T];
__device__ float g_h6[NB*16*14*14*T];
__device__ float g_h7[NB*32*14*14*T];
__device__ float g_h8[NB*128*T];
__device__ float g_dummy[32];

// ---------------- packed f32x2 helpers (sm_103a FFMA2) ----------------
__device__ __forceinline__ void ffma2(unsigned long long& acc,
                                      unsigned long long a,
                                      unsigned long long b) {
    asm("fma.rn.f32x2 %0, %1, %2, %0;" : "+l"(acc) : "l"(a), "l"(b));
}
__device__ __forceinline__ unsigned long long pack2(float v) {
    unsigned long long p;
    asm("mov.b64 %0, {%1, %1};" : "=l"(p) : "f"(v));
    return p;
}
__device__ __forceinline__ void unpack2(unsigned long long p, float& lo, float& hi) {
    asm("mov.b64 {%0, %1}, %2;" : "=f"(lo), "=f"(hi) : "l"(p));
}
__device__ __forceinline__ void cp_async16(void* sdst, const void* gsrc) {
    unsigned sa = (unsigned)__cvta_generic_to_shared(sdst);
    asm volatile("cp.async.cg.shared.global [%0], [%1], 16;" :: "r"(sa), "l"(gsrc));
}
#define CP_COMMIT() asm volatile("cp.async.commit_group;")
#define CP_WAIT1()  asm volatile("cp.async.wait_group 1;")
#define CP_WAIT0()  asm volatile("cp.async.wait_group 0;")

// =====================================================================
// Profiler slot shifter — keeps ncu's fixed capture slot on conv2.
// =====================================================================
__global__ void dummy_kernel(float* p) {
    if (threadIdx.x == 0) p[0] = 1.0f;
}

// =====================================================================
// Row-pair pipelined 3x3 conv 32->32 (28x28) + bias + residual + LIF.
//  - stage = (row-pair, 4-channel chunk): 4 shared input rows feed
//    2 output rows -> cp.async per output row cut 1.4x vs single-row
//  - warp = 32 out-channels x 2 px x 2 rows; rolling ky weights:
//    73 LDS per cc for 288 FFMA2 (L1-per-FMA cut ~17% overall)
//  - triple-buffered cp.async chunks, ONE __syncthreads per stage
//  - per-accumulator FMA order identical to prior kernel (bit-exact)
// =====================================================================
template<bool RES>
__global__ void __launch_bounds__(224, 2)
conv33_pair_kernel(const float* __restrict__ in,
                   const float* __restrict__ wt,
                   const float* __restrict__ bias,
                   const float* __restrict__ res,
                   float* __restrict__ out)
{
    constexpr int CIN = 32, COUT = 32, H = 28, W = 28;
    constexpr int PIX = 14, CCH = 4, RPB = 7;   // 14-px strip, 7 row-pairs/block
    constexpr int ICOLS = PIX + 2;              // 16
    constexpr int CKK   = CIN*9;                // 288
    constexpr int WSTR  = COUT + 1;             // 33 (conflict-free STS+LDS)
    constexpr int WPAD  = CKK*WSTR;             // 9504 floats
    constexpr int BUFSZ = CCH*4*ICOLS*T;        // 4096 floats per buffer
    constexpr int NCH   = CIN/CCH;              // 8 chunks per row-pair
    constexpr int S     = RPB*NCH;              // 56 pipeline stages
    constexpr int THREADS = 224;

    extern __shared__ float smem[];
    float* wsh  = smem;                         // [CKK][WSTR]
    float* buf0 = smem + WPAD;
    float* buf1 = buf0 + BUFSZ;
    float* buf2 = buf1 + BUFSZ;

    const int n   = blockIdx.z;
    const int p0  = blockIdx.y * RPB;           // first row-pair index
    const int w0  = blockIdx.x * PIX;
    const int tid = threadIdx.x;

    // weights once per block (coalesced LDG, conflict-free STS)
    for (int i = tid; i < COUT*CKK; i += THREADS) {
        int ck = i % CKK; int o = i / CKK;
        wsh[ck*WSTR + o] = wt[i];
    }

    const int o    = tid & 31;                  // output channel
    const int pl0  = (tid >> 5) * 2;            // warp -> 2-pixel group
    const float bv = bias[o];

    // ---- stage loader: (row-pair, 4-channel) 4-input-row chunk ----
    auto load_stage = [&](int s, float* b) {
        const int pr = p0 + s/NCH;              // row-pair (out rows 2pr,2pr+1)
        const int c0 = (s % NCH) * CCH;
        const int yb = 2*pr - 1;                // input rows yb .. yb+3
        constexpr int CNT = CCH*4*ICOLS*(T/4);  // 1024 x 16B
        for (int i = tid; i < CNT; i += THREADS) {
            int tq   = i & 3;
            int rest = i >> 2;
            int rx   = rest % ICOLS;
            int ry   = (rest/ICOLS) & 3;
            int cc   = rest/(ICOLS*4);
            int y = yb + ry;
            int x = w0 - 1 + rx;
            float* dst = &b[((cc*4 + ry)*ICOLS + rx)*T + tq*4];
            if ((unsigned)y < (unsigned)H && (unsigned)x < (unsigned)W) {
                const float* src = in
                    + ((size_t)((n*CIN + c0 + cc)*H + y)*W + x)*T + tq*4;
                cp_async16(dst, src);
            } else {
                *reinterpret_cast<float4*>(dst) = make_float4(0.f,0.f,0.f,0.f);
            }
        }
    };

    auto buf_of = [&](int s) -> float* {
        int m = s % 3;
        return m == 0 ? buf0 : (m == 1 ? buf1 : buf2);
    };

    unsigned long long acc[2][2][8];   // [row][px][t-pair]

    load_stage(0, buf0); CP_COMMIT();
    load_stage(1, buf1); CP_COMMIT();

    for (int s = 0; s < S; s++) {
        if (s < S-1) { CP_WAIT1(); } else { CP_WAIT0(); }
        __syncthreads();   // stage-s data visible; compute(s-1) reads retired

        // prefetch s+2 into the buffer freed by compute(s-1)
        if (s + 2 < S) { load_stage(s+2, buf_of(s+2)); CP_COMMIT(); }

        float* cur = buf_of(s);
        const int ci = s % NCH;
        const int c0 = ci * CCH;
        if (ci == 0) {
#pragma unroll
            for (int r = 0; r < 2; r++)
#pragma unroll
                for (int p = 0; p < 2; p++)
#pragma unroll
                    for (int q = 0; q < 8; q++) acc[r][p][q] = 0ULL;
        }

#pragma unroll
        for (int cc = 0; cc < CCH; cc++) {
            unsigned long long wcur[3], wprev[3];
#pragma unroll
            for (int ry = 0; ry < 4; ry++) {    // 4 shared input rows
                if (ry < 3) {
#pragma unroll
                    for (int kx = 0; kx < 3; kx++)
                        wcur[kx] = pack2(wsh[((c0+cc)*9 + ry*3 + kx)*WSTR + o]);
                }
                const float* rowp = &cur[((cc*4 + ry)*ICOLS + pl0)*T];
#pragma unroll
                for (int q = 0; q < 4; q++) {   // t-quarters
                    ulonglong2 cv[4];           // 4-col window (2px + 3kx - 1)
#pragma unroll
                    for (int j = 0; j < 4; j++)
                        cv[j] = *reinterpret_cast<const ulonglong2*>(
                            &rowp[j*T + q*4]);
                    if (ry < 3) {               // out row 0, ky = ry
#pragma unroll
                        for (int kx = 0; kx < 3; kx++)
#pragma unroll
                            for (int p = 0; p < 2; p++) {
                                ffma2(acc[0][p][q*2+0], cv[kx+p].x, wcur[kx]);
                                ffma2(acc[0][p][q*2+1], cv[kx+p].y, wcur[kx]);
                            }
                    }
                    if (ry > 0) {               // out row 1, ky = ry-1
#pragma unroll
                        for (int kx = 0; kx < 3; kx++)
#pragma unroll
                            for (int p = 0; p < 2; p++) {
                                ffma2(acc[1][p][q*2+0], cv[kx+p].x, wprev[kx]);
                                ffma2(acc[1][p][q*2+1], cv[kx+p].y, wprev[kx]);
                            }
                    }
                }
#pragma unroll
                for (int kx = 0; kx < 3; kx++) wprev[kx] = wcur[kx];
            }
        }

        if (ci == NCH-1) {   // row-pair complete -> LIF epilogue
            const int hr = 2*(p0 + s/NCH);
#pragma unroll
            for (int r = 0; r < 2; r++)
#pragma unroll
                for (int p = 0; p < 2; p++) {
                    float a[T];
#pragma unroll
                    for (int q = 0; q < 8; q++)
                        unpack2(acc[r][p][q], a[2*q], a[2*q+1]);
                    const int w = w0 + pl0 + p;
                    const size_t ob =
                        ((size_t)((n*COUT + o)*H + hr + r)*W + w)*T;

                    float rv[T];
                    if (RES) {
                        const float4* rp =
                            reinterpret_cast<const float4*>(res + ob);
#pragma unroll
                        for (int q = 0; q < 4; q++) {
                            float4 v = rp[q];
                            rv[4*q+0]=v.x; rv[4*q+1]=v.y;
                            rv[4*q+2]=v.z; rv[4*q+3]=v.w;
                        }
                    } else {
#pragma unroll
                        for (int t = 0; t < T; t++) rv[t] = 0.f;
                    }

                    float u = 0.f, sb[T];
#pragma unroll
                    for (int t = 0; t < T; t++) {
                        u += a[t] + bv + rv[t];
                        float sp = (u >= 1.0f) ? 1.0f : 0.0f;
                        sb[t] = sp;
                        u -= sp;
                    }
                    float4* op = reinterpret_cast<float4*>(out + ob);
#pragma unroll
                    for (int q = 0; q < 4; q++)
                        op[q] = make_float4(sb[4*q+0], sb[4*q+1],
                                            sb[4*q+2], sb[4*q+3]);
                }
        }
    }
}

// =====================================================================
// Generic fused conv + bias + residual + LIF (small layers).
// =====================================================================
template<int CIN,int COUT,int H,int W,int KS,int PAD,int PIX,int CCH,int RB,bool RES>
__global__ void __launch_bounds__(32*PIX/(32/COUT))
conv_spike_kernel(const float* __restrict__ in,
                  const float* __restrict__ wt,
                  const float* __restrict__ bias,
                  const float* __restrict__ res,
                  float* __restrict__ out)
{
    constexpr int PPW     = 32/COUT;
    constexpr int THREADS = 32*PIX/PPW;
    constexpr int CKK     = CIN*KS*KS;
    constexpr int WSTR    = COUT + 1;
    constexpr int WPAD    = (CKK*WSTR + 3) & ~3;
    constexpr int ICOLS   = PIX + KS - 1;
    constexpr int NCH     = CIN/CCH;

    extern __shared__ float smem[];
    float* wsh = smem;
    float* ish = smem + WPAD;

    const int n   = blockIdx.z;
    const int h0  = blockIdx.y * RB;
    const int w0  = blockIdx.x * PIX;
    const int tid = threadIdx.x;

    for (int i = tid; i < COUT*CKK; i += THREADS) {
        int ck = i % CKK; int o = i / CKK;
        wsh[ck*WSTR + o] = wt[i];
    }

    const int lane = tid & 31;
    const int wp   = tid >> 5;
    const int o    = lane % COUT;
    const int pl   = wp*PPW + lane/COUT;
    const int w    = w0 + pl;
    const float b  = bias[o];

    for (int h = h0; h < h0 + RB; h++) {
        unsigned long long acc2[T/2];
#pragma unroll
        for (int q = 0; q < T/2; q++) acc2[q] = 0ULL;

        for (int ch = 0; ch < NCH; ch++) {
            const int c0 = ch*CCH;
            __syncthreads();
            constexpr int I4 = CCH*KS*ICOLS*(T/4);
            float4* ish4 = reinterpret_cast<float4*>(ish);
            for (int i = tid; i < I4; i += THREADS) {
                int tq   = i & 3;
                int rest = i >> 2;
                int rx   = rest % ICOLS;
                int ry   = (rest/ICOLS) % KS;
                int cc   = rest/(ICOLS*KS);
                int y = h  - PAD + ry;
                int x = w0 - PAD + rx;
                float4 v = make_float4(0.f,0.f,0.f,0.f);
                if (y >= 0 && y < H && x >= 0 && x < W)
                    v = reinterpret_cast<const float4*>(in)
                          [((size_t)((n*CIN + c0 + cc)*H + y)*W + x)*(T/4) + tq];
                ish4[i] = v;
            }
            __syncthreads();

#pragma unroll
            for (int cc = 0; cc < CCH; cc++) {
#pragma unroll
                for (int ky = 0; ky < KS; ky++) {
#pragma unroll
                    for (int kx = 0; kx < KS; kx++) {
                        float wv = wsh[(((c0+cc)*KS + ky)*KS + kx)*WSTR + o];
                        unsigned long long w2 = pack2(wv);
                        const ulonglong2* iv = reinterpret_cast<const ulonglong2*>(
                            &ish[((cc*KS + ky)*ICOLS + pl + kx)*T]);
#pragma unroll
                        for (int q = 0; q < 4; q++) {
                            ulonglong2 v = iv[q];
                            ffma2(acc2[2*q+0], v.x, w2);
                            ffma2(acc2[2*q+1], v.y, w2);
                        }
                    }
                }
            }
        }

        float acc[T];
#pragma unroll
        for (int q = 0; q < T/2; q++) unpack2(acc2[q], acc[2*q], acc[2*q+1]);

        const size_t obase = ((size_t)((n*COUT + o)*H + h)*W + w)*T;

        float r[T];
        if (RES) {
            const float4* rp = reinterpret_cast<const float4*>(res + obase);
#pragma unroll
            for (int q = 0; q < 4; q++) {
                float4 rv = rp[q];
                r[4*q+0]=rv.x; r[4*q+1]=rv.y; r[4*q+2]=rv.z; r[4*q+3]=rv.w;
            }
        } else {
#pragma unroll
            for (int t = 0; t < T; t++) r[t] = 0.f;
        }

        float u = 0.f;
        float s[T];
#pragma unroll
        for (int t = 0; t < T; t++) {
            u += acc[t] + b + r[t];
            float sp = (u >= 1.0f) ? 1.0f : 0.0f;
            s[t] = sp;
            u -= sp;
        }
        float4* op = reinterpret_cast<float4*>(out + obase);
#pragma unroll
        for (int q = 0; q < 4; q++)
            op[q] = make_float4(s[4*q+0], s[4*q+1], s[4*q+2], s[4*q+3]);
    }
}

// =====================================================================
// 2x2 average pool (28->14) fused with spike scan.
// =====================================================================
__global__ void pool_spike_kernel(const float* __restrict__ in,
                                  float* __restrict__ out)
{
    int idx = blockIdx.x*blockDim.x + threadIdx.x;
    if (idx >= NB*32*14*14) return;
    int w  = idx % 14;
    int h  = (idx / 14) % 14;
    int nc = idx / 196;
    const float4* i00 = reinterpret_cast<const float4*>(
        in + ((size_t)(nc*28 + 2*h  )*28 + 2*w)*T);
    const float4* i10 = reinterpret_cast<const float4*>(
        in + ((size_t)(nc*28 + 2*h+1)*28 + 2*w)*T);
    float u = 0.f;
    float s[T];
#pragma unroll
    for (int q = 0; q < 4; q++) {
        float4 a = i00[q], b = i00[q+4], c = i10[q], d = i10[q+4];
        float vv[4] = {(a.x+b.x+c.x+d.x)*0.25f, (a.y+b.y+c.y+d.y)*0.25f,
                       (a.z+b.z+c.z+d.z)*0.25f, (a.w+b.w+c.w+d.w)*0.25f};
#pragma unroll
        for (int j = 0; j < 4; j++) {
            u += vv[j];
            float sp = (u >= 1.0f) ? 1.0f : 0.0f;
            s[4*q+j] = sp;
            u -= sp;
        }
    }
    float4* op = reinterpret_cast<float4*>(out + (size_t)idx*T);
#pragma unroll
    for (int q = 0; q < 4; q++)
        op[q] = make_float4(s[4*q+0], s[4*q+1], s[4*q+2], s[4*q+3]);
}

// =====================================================================
// Dense1: [N, 6272, T] x [128, 6272] -> spike -> [N, 128, T]
// =====================================================================
__global__ void dense1_kernel(const float* __restrict__ act,
                              const float* __restrict__ wt,
                              const float* __restrict__ bias,
                              float* __restrict__ out)
{
    const int lane = threadIdx.x & 31;
    const int warp = threadIdx.x >> 5;
    const int n  = blockIdx.y;
    const int o0 = blockIdx.x*32 + warp*4;

    unsigned long long acc2[4][8];
#pragma unroll
    for (int j = 0; j < 4; j++)
#pragma unroll
        for (int q = 0; q < 8; q++) acc2[j][q] = 0ULL;

    const ulonglong2* ab = reinterpret_cast<const ulonglong2*>(act + (size_t)n*6272*T);
    for (int f = lane; f < 6272; f += 32) {
        ulonglong2 a0 = ab[f*4+0], a1 = ab[f*4+1], a2 = ab[f*4+2], a3 = ab[f*4+3];
#pragma unroll
        for (int j = 0; j < 4; j++) {
            unsigned long long w2 = pack2(wt[(size_t)(o0+j)*6272 + f]);
            ffma2(acc2[j][0], a0.x, w2); ffma2(acc2[j][1], a0.y, w2);
            ffma2(acc2[j][2], a1.x, w2); ffma2(acc2[j][3], a1.y, w2);
            ffma2(acc2[j][4], a2.x, w2); ffma2(acc2[j][5], a2.y, w2);
            ffma2(acc2[j][6], a3.x, w2); ffma2(acc2[j][7], a3.y, w2);
        }
    }

    float acc[4][16];
#pragma unroll
    for (int j = 0; j < 4; j++)
#pragma unroll
        for (int q = 0; q < 8; q++) unpack2(acc2[j][q], acc[j][2*q], acc[j][2*q+1]);

#pragma unroll
    for (int j = 0; j < 4; j++)
#pragma unroll
        for (int t = 0; t < 16; t++)
#pragma unroll
            for (int off = 16; off; off >>= 1)
                acc[j][t] += __shfl_xor_sync(0xffffffffu, acc[j][t], off);

    if (lane == 0) {
#pragma unroll
        for (int j = 0; j < 4; j++) {
            float b = bias[o0+j];
            float u = 0.f;
            float s[16];
#pragma unroll
            for (int t = 0; t < 16; t++) {
                u += acc[j][t] + b;
                float sp = (u >= 1.0f) ? 1.0f : 0.0f;
                s[t] = sp; u -= sp;
            }
            float4* op4 = reinterpret_cast<float4*>(out + ((size_t)n*128 + o0 + j)*T);
#pragma unroll
            for (int q = 0; q < 4; q++)
                op4[q] = make_float4(s[4*q+0], s[4*q+1], s[4*q+2], s[4*q+3]);
        }
    }
}

// =====================================================================
// Dense2 + spike + firing-rate reduction -> out [N, 10]
// =====================================================================
__global__ void dense2_kernel(const float* __restrict__ h8,
                              const float* __restrict__ wt,
                              const float* __restrict__ bias,
                              float* __restrict__ out)
{
    const int lane = threadIdx.x & 31;
    const int warp = threadIdx.x >> 5;
    const int gw = blockIdx.x*8 + warp;
    if (gw >= NB*10) return;
    const int n = gw / 10, o = gw % 10;

    float acc[16];
#pragma unroll
    for (int t = 0; t < 16; t++) acc[t] = 0.f;

    for (int f = lane; f < 128; f += 32) {
        const float4* av = reinterpret_cast<const float4*>(h8 + ((size_t)n*128 + f)*T);
        float wv = wt[o*128 + f];
        float4 a0 = av[0], a1 = av[1], a2 = av[2], a3 = av[3];
        acc[0] +=wv*a0.x; acc[1] +=wv*a0.y; acc[2] +=wv*a0.z; acc[3] +=wv*a0.w;
        acc[4] +=wv*a1.x; acc[5] +=wv*a1.y; acc[6] +=wv*a1.z; acc[7] +=wv*a1.w;
        acc[8] +=wv*a2.x; acc[9] +=wv*a2.y; acc[10]+=wv*a2.z; acc[11]+=wv*a2.w;
        acc[12]+=wv*a3.x; acc[13]+=wv*a3.y; acc[14]+=wv*a3.z; acc[15]+=wv*a3.w;
    }
#pragma unroll
    for (int t = 0; t < 16; t++)
#pragma unroll
        for (int off = 16; off; off >>= 1)
            acc[t] += __shfl_xor_sync(0xffffffffu, acc[t], off);

    if (lane == 0) {
        float b = bias[o];
        float u = 0.f, ssum = 0.f;
#pragma unroll
        for (int t = 0; t < 16; t++) {
            u += acc[t] + b;
            float sp = (u >= 1.0f) ? 1.0f : 0.0f;
            ssum += sp; u -= sp;
        }
        out[n*10 + o] = ssum * (1.0f/16.0f);
    }
}

// ---------------------------------------------------------------------
static inline int conv_smem(int cin, int cout, int ks, int pix, int cch) {
    int ckk  = cin*ks*ks;
    int wpad = (ckk*(cout+1) + 3) & ~3;
    return (wpad + cch*ks*(pix+ks-1)*T) * (int)sizeof(float);
}

extern "C" void kernel_launch(void* const* d_in, const int* /*in_sizes*/, int /*n_in*/,
                              void* d_out, int /*out_size*/)
{
    const float* x   = (const float*)d_in[0];
    const float* w1  = (const float*)d_in[1];
    const float* b1  = (const float*)d_in[2];
    const float* w2  = (const float*)d_in[3];
    const float* b2  = (const float*)d_in[4];
    const float* w3  = (const float*)d_in[5];
    const float* b3  = (const float*)d_in[6];
    const float* w4  = (const float*)d_in[7];
    const float* b4  = (const float*)d_in[8];
    const float* w5  = (const float*)d_in[9];
    const float* b5  = (const float*)d_in[10];
    const float* w6  = (const float*)d_in[11];
    const float* b6  = (const float*)d_in[12];
    const float* wf1 = (const float*)d_in[13];
    const float* bf1 = (const float*)d_in[14];
    const float* wf2 = (const float*)d_in[15];
    const float* bf2 = (const float*)d_in[16];
    float* out = (float*)d_out;

    float *h1,*h2,*h3,*h4,*h5,*h6,*h7,*h8,*dm;
    cudaGetSymbolAddress((void**)&h1, g_h1);
    cudaGetSymbolAddress((void**)&h2, g_h2);
    cudaGetSymbolAddress((void**)&h3, g_h3);
    cudaGetSymbolAddress((void**)&h4, g_h4);
    cudaGetSymbolAddress((void**)&h5, g_h5);
    cudaGetSymbolAddress((void**)&h6, g_h6);
    cudaGetSymbolAddress((void**)&h7, g_h7);
    cudaGetSymbolAddress((void**)&h8, g_h8);
    cudaGetSymbolAddress((void**)&dm, g_dummy);

    // row-pair conv2/3 smem: weights 9504 + 3x4096 floats = 87168 B
    const int smP = (9504 + 3*4096) * (int)sizeof(float);
    cudaFuncSetAttribute(conv33_pair_kernel<false>,
                         cudaFuncAttributeMaxDynamicSharedMemorySize, smP);
    cudaFuncSetAttribute(conv33_pair_kernel<true>,
                         cudaFuncAttributeMaxDynamicSharedMemorySize, smP);

    const int sm1 = conv_smem(1,32,3,14,1);
    const int sm4 = conv_smem(32,16,1,14,8);
    const int sm5 = conv_smem(16,16,3,14,8);
    const int sm6 = conv_smem(16,32,1,14,16);

    // --- two no-op launches: keep ncu's capture slot on conv2 ---
    dummy_kernel<<<1, 32>>>(dm);
    dummy_kernel<<<1, 32>>>(dm);

    // L1: conv 1->32 3x3 pad1 + spike (RB=2 -> 3584 blocks)
    conv_spike_kernel<1,32,28,28,3,1,14,1,2,false>
        <<<dim3(2,14,NB), 32*14, sm1>>>(x, w1, b1, nullptr, h1);
    // L2: conv 32->32 3x3 pad1 + spike (row-pair pipelined)
    conv33_pair_kernel<false>
        <<<dim3(2,2,NB), 224, smP>>>(h1, w2, b2, nullptr, h2);
    // L3: conv 32->32 3x3 pad1 + residual(h1) + spike
    conv33_pair_kernel<true>
        <<<dim3(2,2,NB), 224, smP>>>(h2, w3, b3, h1, h3);
    // pool 2x2 + spike
    pool_spike_kernel<<<(NB*32*14*14 + 255)/256, 256>>>(h3, h4);
    // L4: conv 32->16 1x1 + spike (RB=1 -> 1792 blocks)
    conv_spike_kernel<32,16,14,14,1,0,14,8,1,false>
        <<<dim3(1,14,NB), 224, sm4>>>(h4, w4, b4, nullptr, h5);
    // L5: conv 16->16 3x3 pad1 + spike (RB=1 -> 1792 blocks)
    conv_spike_kernel<16,16,14,14,3,1,14,8,1,false>
        <<<dim3(1,14,NB), 224, sm5>>>(h5, w5, b5, nullptr, h6);
    // L6: conv 16->32 1x1 + residual(h4) + spike (RB=1 -> 1792 blocks)
    conv_spike_kernel<16,32,14,14,1,0,14,16,1,true>
        <<<dim3(1,14,NB), 448, sm6>>>(h6, w6, b6, h4, h7);
    // dense1 6272->128 + spike
    dense1_kernel<<<dim3(4,NB), 256>>>(h7, wf1, bf1, h8);
    // dense2 128->10 + spike + rate
    dense2_kernel<<<(NB*10 + 7)/8, 256>>>(h8, wf2, bf2, out);
}

// round 12
// speedup vs baseline: 1.0923x; 1.0923x over previous
#include <cuda_runtime.h>
#include <cstdint>
#include <cstddef>

constexpr int T  = 16;   // timesteps (innermost, contiguous)
constexpr int NB = 128;  // batch

// ---------------- static scratch (allocation-free) ----------------
__device__ float g_h1[NB*32*28*28*T];   // 205 MB
__device__ float g_h2[NB*32*28*28*T];
__device__ float g_h4[NB*32*14*14*T];
__device__ float g_h5[NB*16*14*14*T];
__device__ float g_h6[NB*16*14*14*T];
__device__ float g_h7[NB*32*14*14*T];
__device__ float g_h8[NB*128*T];
__device__ float g_dummy[32];

// ---------------- packed f32x2 helpers (sm_103a FFMA2) ----------------
__device__ __forceinline__ void ffma2(unsigned long long& acc,
                                      unsigned long long a,
                                      unsigned long long b) {
    asm("fma.rn.f32x2 %0, %1, %2, %0;" : "+l"(acc) : "l"(a), "l"(b));
}
__device__ __forceinline__ unsigned long long pack2(float v) {
    unsigned long long p;
    asm("mov.b64 %0, {%1, %1};" : "=l"(p) : "f"(v));
    return p;
}
__device__ __forceinline__ void unpack2(unsigned long long p, float& lo, float& hi) {
    asm("mov.b64 {%0, %1}, %2;" : "=f"(lo), "=f"(hi) : "l"(p));
}
__device__ __forceinline__ void cp_async16(void* sdst, const void* gsrc) {
    unsigned sa = (unsigned)__cvta_generic_to_shared(sdst);
    asm volatile("cp.async.cg.shared.global [%0], [%1], 16;" :: "r"(sa), "l"(gsrc));
}
#define CP_COMMIT() asm volatile("cp.async.commit_group;")
#define CP_WAIT1()  asm volatile("cp.async.wait_group 1;")
#define CP_WAIT0()  asm volatile("cp.async.wait_group 0;")

// =====================================================================
// Profiler slot shifter — keeps ncu's fixed capture slot on conv2.
// =====================================================================
__global__ void dummy_kernel(float* p) {
    if (threadIdx.x == 0) p[0] = 1.0f;
}

// =====================================================================
// Pipelined 3x3 conv 32->32 (28x28) + bias + optional residual + LIF,
// optionally FUSED with 2x2 avg-pool + pool-LIF (POOL=true: conv spikes
// are bitpacked in registers, never written; pooled spikes go to out
// at 14x14 resolution).
//  - 224 threads / 7 warps; warp = 32 out-channels x 4 pixels/thread
//  - triple-buffered cp.async chunks (4 ch), ONE __syncthreads/stage
//  - block processes RB=4 rows (2 aligned row-pairs for pooling)
// =====================================================================
template<bool RES, bool POOL>
__global__ void __launch_bounds__(224, 2)
conv33_pipe_kernel(const float* __restrict__ in,
                   const float* __restrict__ wt,
                   const float* __restrict__ bias,
                   const float* __restrict__ res,
                   float* __restrict__ out)
{
    constexpr int CIN = 32, COUT = 32, H = 28, W = 28, KS = 3, PAD = 1;
    constexpr int PIX = 28, CCH = 4, RB = 4;
    constexpr int ICOLS = PIX + KS - 1;        // 30
    constexpr int CKK   = CIN*KS*KS;           // 288
    constexpr int WSTR  = COUT + 1;            // 33 (conflict-free STS+LDS)
    constexpr int WPAD  = CKK*WSTR;            // 9504 floats
    constexpr int BUFSZ = CCH*KS*ICOLS*T;      // 5760 floats per buffer
    constexpr int NCH   = CIN/CCH;             // 8 chunks per row
    constexpr int S     = RB*NCH;              // 32 pipeline stages
    constexpr int THREADS = 224;

    extern __shared__ float smem[];
    float* wsh  = smem;                        // [CKK][WSTR]
    float* buf0 = smem + WPAD;
    float* buf1 = buf0 + BUFSZ;
    float* buf2 = buf1 + BUFSZ;

    const int n   = blockIdx.z;
    const int h0  = blockIdx.y * RB;           // even (RB=4)
    const int tid = threadIdx.x;

    // weights once per block (coalesced LDG, conflict-free STS)
    for (int i = tid; i < COUT*CKK; i += THREADS) {
        int ck = i % CKK; int o = i / CKK;
        wsh[ck*WSTR + o] = wt[i];
    }

    const int lane = tid & 31;     // output channel
    const int wp   = tid >> 5;     // warp -> 4-pixel group
    const int o    = lane;
    const int pl0  = wp*4;
    const float bv = bias[o];

    // ---- stage loader: (row, 4 channels) chunk via cp.async ----
    auto load_stage = [&](int s, float* b) {
        const int hh = h0 + s/NCH;
        const int c0 = (s % NCH) * CCH;
        constexpr int CNT = CCH*KS*ICOLS*(T/4);   // 1440 x 16B
        for (int i = tid; i < CNT; i += THREADS) {
            int tq   = i & 3;
            int rest = i >> 2;
            int rx   = rest % ICOLS;
            int ry   = (rest/ICOLS) % KS;
            int cc   = rest/(ICOLS*KS);
            int y = hh - PAD + ry;
            int x =    - PAD + rx;
            float* dst = &b[((cc*KS + ry)*ICOLS + rx)*T + tq*4];
            if (y >= 0 && y < H && x >= 0 && x < W) {
                const float4* src = reinterpret_cast<const float4*>(in)
                    + ((size_t)((n*CIN + c0 + cc)*H + y)*W + x)*(T/4) + tq;
                cp_async16(dst, src);
            } else {
                *reinterpret_cast<float4*>(dst) = make_float4(0.f,0.f,0.f,0.f);
            }
        }
    };

    auto buf_of = [&](int s) -> float* {
        int m = s % 3;
        return m == 0 ? buf0 : (m == 1 ? buf1 : buf2);
    };

    unsigned long long acc2[4][8];   // [pixel][t-pair]
    unsigned long long ebits = 0ULL; // POOL: even-row spikes, 4px x 16t bits

    load_stage(0, buf0); CP_COMMIT();
    load_stage(1, buf1); CP_COMMIT();

    for (int s = 0; s < S; s++) {
        if (s < S-1) { CP_WAIT1(); } else { CP_WAIT0(); }
        __syncthreads();   // stage-s data visible; compute(s-1) reads retired

        // prefetch s+2 into the buffer freed by compute(s-1)
        if (s + 2 < S) { load_stage(s+2, buf_of(s+2)); CP_COMMIT(); }

        float* cur = buf_of(s);
        const int c0 = (s % NCH) * CCH;
        if ((s % NCH) == 0) {
#pragma unroll
            for (int px = 0; px < 4; px++)
#pragma unroll
                for (int q = 0; q < 8; q++) acc2[px][q] = 0ULL;
        }

#pragma unroll
        for (int cc = 0; cc < CCH; cc++) {
#pragma unroll
            for (int ky = 0; ky < KS; ky++) {
                unsigned long long ws[KS];
#pragma unroll
                for (int kx = 0; kx < KS; kx++)
                    ws[kx] = pack2(wsh[(((c0+cc)*KS + ky)*KS + kx)*WSTR + o]);
                const float* rowp = &cur[((cc*KS + ky)*ICOLS + pl0)*T];
#pragma unroll
                for (int th = 0; th < 4; th++) {   // t-quarters (4 t's each)
                    ulonglong2 cv[6];              // 6-column window
#pragma unroll
                    for (int j = 0; j < 6; j++)
                        cv[j] = *reinterpret_cast<const ulonglong2*>(
                            &rowp[j*T + th*4]);
#pragma unroll
                    for (int kx = 0; kx < KS; kx++)
#pragma unroll
                        for (int px = 0; px < 4; px++) {
                            ffma2(acc2[px][th*2+0], cv[kx+px].x, ws[kx]);
                            ffma2(acc2[px][th*2+1], cv[kx+px].y, ws[kx]);
                        }
                }
            }
        }

        if ((s % NCH) == NCH-1) {  // row complete -> epilogue
            const int h = h0 + s/NCH;
            if (!POOL) {
#pragma unroll
                for (int px = 0; px < 4; px++) {
                    float acc[T];
#pragma unroll
                    for (int q = 0; q < 8; q++)
                        unpack2(acc2[px][q], acc[2*q], acc[2*q+1]);
                    const int w = pl0 + px;
                    const size_t obase =
                        ((size_t)((n*COUT + o)*H + h)*W + w)*T;

                    float r[T];
                    if (RES) {
                        const float4* rp =
                            reinterpret_cast<const float4*>(res + obase);
#pragma unroll
                        for (int q = 0; q < 4; q++) {
                            float4 rv = rp[q];
                            r[4*q+0]=rv.x; r[4*q+1]=rv.y;
                            r[4*q+2]=rv.z; r[4*q+3]=rv.w;
                        }
                    } else {
#pragma unroll
                        for (int t = 0; t < T; t++) r[t] = 0.f;
                    }

                    float u = 0.f, sb[T];
#pragma unroll
                    for (int t = 0; t < T; t++) {
                        u += acc[t] + bv + r[t];
                        float sp = (u >= 1.0f) ? 1.0f : 0.0f;
                        sb[t] = sp;
                        u -= sp;
                    }
                    float4* op = reinterpret_cast<float4*>(out + obase);
#pragma unroll
                    for (int q = 0; q < 4; q++)
                        op[q] = make_float4(sb[4*q+0], sb[4*q+1],
                                            sb[4*q+2], sb[4*q+3]);
                }
            } else {
                // POOL path: LIF -> bitpack 4px x 16t spikes (no h3 store)
                unsigned long long rowbits = 0ULL;
#pragma unroll
                for (int px = 0; px < 4; px++) {
                    float acc[T];
#pragma unroll
                    for (int q = 0; q < 8; q++)
                        unpack2(acc2[px][q], acc[2*q], acc[2*q+1]);
                    const int w = pl0 + px;
                    const size_t rbase =
                        ((size_t)((n*COUT + o)*H + h)*W + w)*T;
                    float r[T];
                    if (RES) {
                        const float4* rp =
                            reinterpret_cast<const float4*>(res + rbase);
#pragma unroll
                        for (int q = 0; q < 4; q++) {
                            float4 rv = rp[q];
                            r[4*q+0]=rv.x; r[4*q+1]=rv.y;
                            r[4*q+2]=rv.z; r[4*q+3]=rv.w;
                        }
                    } else {
#pragma unroll
                        for (int t = 0; t < T; t++) r[t] = 0.f;
                    }
                    float u = 0.f;
#pragma unroll
                    for (int t = 0; t < T; t++) {
                        u += acc[t] + bv + r[t];
                        unsigned long long sp = (u >= 1.0f) ? 1ULL : 0ULL;
                        rowbits |= sp << (px*16 + t);
                        u -= (float)sp;
                    }
                }
                if ((h & 1) == 0) {
                    ebits = rowbits;       // stash even row
                } else {
                    // pool window pair: px (2p, 2p+1) from both rows
#pragma unroll
                    for (int p = 0; p < 2; p++) {
                        float u = 0.f, sb[T];
#pragma unroll
                        for (int t = 0; t < T; t++) {
                            int sum = (int)((ebits   >> ((2*p  )*16 + t)) & 1ULL)
                                    + (int)((ebits   >> ((2*p+1)*16 + t)) & 1ULL)
                                    + (int)((rowbits >> ((2*p  )*16 + t)) & 1ULL)
                                    + (int)((rowbits >> ((2*p+1)*16 + t)) & 1ULL);
                            float pooled = 0.25f * (float)sum;
                            u += pooled;
                            float sp = (u >= 1.0f) ? 1.0f : 0.0f;
                            sb[t] = sp;
                            u -= sp;
                        }
                        const int pw = (pl0 >> 1) + p;      // pooled col
                        const int ph = h >> 1;              // pooled row
                        float4* op = reinterpret_cast<float4*>(
                            out + ((size_t)((n*COUT + o)*14 + ph)*14 + pw)*T);
#pragma unroll
                        for (int q = 0; q < 4; q++)
                            op[q] = make_float4(sb[4*q+0], sb[4*q+1],
                                                sb[4*q+2], sb[4*q+3]);
                    }
                }
            }
        }
    }
}

// =====================================================================
// Generic fused conv + bias + residual + LIF (small layers).
// =====================================================================
template<int CIN,int COUT,int H,int W,int KS,int PAD,int PIX,int CCH,int RB,bool RES>
__global__ void __launch_bounds__(32*PIX/(32/COUT))
conv_spike_kernel(const float* __restrict__ in,
                  const float* __restrict__ wt,
                  const float* __restrict__ bias,
                  const float* __restrict__ res,
                  float* __restrict__ out)
{
    constexpr int PPW     = 32/COUT;
    constexpr int THREADS = 32*PIX/PPW;
    constexpr int CKK     = CIN*KS*KS;
    constexpr int WSTR    = COUT + 1;
    constexpr int WPAD    = (CKK*WSTR + 3) & ~3;
    constexpr int ICOLS   = PIX + KS - 1;
    constexpr int NCH     = CIN/CCH;

    extern __shared__ float smem[];
    float* wsh = smem;
    float* ish = smem + WPAD;

    const int n   = blockIdx.z;
    const int h0  = blockIdx.y * RB;
    const int w0  = blockIdx.x * PIX;
    const int tid = threadIdx.x;

    for (int i = tid; i < COUT*CKK; i += THREADS) {
        int ck = i % CKK; int o = i / CKK;
        wsh[ck*WSTR + o] = wt[i];
    }

    const int lane = tid & 31;
    const int wp   = tid >> 5;
    const int o    = lane % COUT;
    const int pl   = wp*PPW + lane/COUT;
    const int w    = w0 + pl;
    const float b  = bias[o];

    for (int h = h0; h < h0 + RB; h++) {
        unsigned long long acc2[T/2];
#pragma unroll
        for (int q = 0; q < T/2; q++) acc2[q] = 0ULL;

        for (int ch = 0; ch < NCH; ch++) {
            const int c0 = ch*CCH;
            __syncthreads();
            constexpr int I4 = CCH*KS*ICOLS*(T/4);
            float4* ish4 = reinterpret_cast<float4*>(ish);
            for (int i = tid; i < I4; i += THREADS) {
                int tq   = i & 3;
                int rest = i >> 2;
                int rx   = rest % ICOLS;
                int ry   = (rest/ICOLS) % KS;
                int cc   = rest/(ICOLS*KS);
                int y = h  - PAD + ry;
                int x = w0 - PAD + rx;
                float4 v = make_float4(0.f,0.f,0.f,0.f);
                if (y >= 0 && y < H && x >= 0 && x < W)
                    v = reinterpret_cast<const float4*>(in)
                          [((size_t)((n*CIN + c0 + cc)*H + y)*W + x)*(T/4) + tq];
                ish4[i] = v;
            }
            __syncthreads();

#pragma unroll
            for (int cc = 0; cc < CCH; cc++) {
#pragma unroll
                for (int ky = 0; ky < KS; ky++) {
#pragma unroll
                    for (int kx = 0; kx < KS; kx++) {
                        float wv = wsh[(((c0+cc)*KS + ky)*KS + kx)*WSTR + o];
                        unsigned long long w2 = pack2(wv);
                        const ulonglong2* iv = reinterpret_cast<const ulonglong2*>(
                            &ish[((cc*KS + ky)*ICOLS + pl + kx)*T]);
#pragma unroll
                        for (int q = 0; q < 4; q++) {
                            ulonglong2 v = iv[q];
                            ffma2(acc2[2*q+0], v.x, w2);
                            ffma2(acc2[2*q+1], v.y, w2);
                        }
                    }
                }
            }
        }

        float acc[T];
#pragma unroll
        for (int q = 0; q < T/2; q++) unpack2(acc2[q], acc[2*q], acc[2*q+1]);

        const size_t obase = ((size_t)((n*COUT + o)*H + h)*W + w)*T;

        float r[T];
        if (RES) {
            const float4* rp = reinterpret_cast<const float4*>(res + obase);
#pragma unroll
            for (int q = 0; q < 4; q++) {
                float4 rv = rp[q];
                r[4*q+0]=rv.x; r[4*q+1]=rv.y; r[4*q+2]=rv.z; r[4*q+3]=rv.w;
            }
        } else {
#pragma unroll
            for (int t = 0; t < T; t++) r[t] = 0.f;
        }

        float u = 0.f;
        float s[T];
#pragma unroll
        for (int t = 0; t < T; t++) {
            u += acc[t] + b + r[t];
            float sp = (u >= 1.0f) ? 1.0f : 0.0f;
            s[t] = sp;
            u -= sp;
        }
        float4* op = reinterpret_cast<float4*>(out + obase);
#pragma unroll
        for (int q = 0; q < 4; q++)
            op[q] = make_float4(s[4*q+0], s[4*q+1], s[4*q+2], s[4*q+3]);
    }
}

// =====================================================================
// Dense1: [N, 6272, T] x [128, 6272] -> spike -> [N, 128, T]
// =====================================================================
__global__ void dense1_kernel(const float* __restrict__ act,
                              const float* __restrict__ wt,
                              const float* __restrict__ bias,
                              float* __restrict__ out)
{
    const int lane = threadIdx.x & 31;
    const int warp = threadIdx.x >> 5;
    const int n  = blockIdx.y;
    const int o0 = blockIdx.x*32 + warp*4;

    unsigned long long acc2[4][8];
#pragma unroll
    for (int j = 0; j < 4; j++)
#pragma unroll
        for (int q = 0; q < 8; q++) acc2[j][q] = 0ULL;

    const ulonglong2* ab = reinterpret_cast<const ulonglong2*>(act + (size_t)n*6272*T);
    for (int f = lane; f < 6272; f += 32) {
        ulonglong2 a0 = ab[f*4+0], a1 = ab[f*4+1], a2 = ab[f*4+2], a3 = ab[f*4+3];
#pragma unroll
        for (int j = 0; j < 4; j++) {
            unsigned long long w2 = pack2(wt[(size_t)(o0+j)*6272 + f]);
            ffma2(acc2[j][0], a0.x, w2); ffma2(acc2[j][1], a0.y, w2);
            ffma2(acc2[j][2], a1.x, w2); ffma2(acc2[j][3], a1.y, w2);
            ffma2(acc2[j][4], a2.x, w2); ffma2(acc2[j][5], a2.y, w2);
            ffma2(acc2[j][6], a3.x, w2); ffma2(acc2[j][7], a3.y, w2);
        }
    }

    float acc[4][16];
#pragma unroll
    for (int j = 0; j < 4; j++)
#pragma unroll
        for (int q = 0; q < 8; q++) unpack2(acc2[j][q], acc[j][2*q], acc[j][2*q+1]);

#pragma unroll
    for (int j = 0; j < 4; j++)
#pragma unroll
        for (int t = 0; t < 16; t++)
#pragma unroll
            for (int off = 16; off; off >>= 1)
                acc[j][t] += __shfl_xor_sync(0xffffffffu, acc[j][t], off);

    if (lane == 0) {
#pragma unroll
        for (int j = 0; j < 4; j++) {
            float b = bias[o0+j];
            float u = 0.f;
            float s[16];
#pragma unroll
            for (int t = 0; t < 16; t++) {
                u += acc[j][t] + b;
                float sp = (u >= 1.0f) ? 1.0f : 0.0f;
                s[t] = sp; u -= sp;
            }
            float4* op4 = reinterpret_cast<float4*>(out + ((size_t)n*128 + o0 + j)*T);
#pragma unroll
            for (int q = 0; q < 4; q++)
                op4[q] = make_float4(s[4*q+0], s[4*q+1], s[4*q+2], s[4*q+3]);
        }
    }
}

// =====================================================================
// Dense2 + spike + firing-rate reduction -> out [N, 10]
// =====================================================================
__global__ void dense2_kernel(const float* __restrict__ h8,
                              const float* __restrict__ wt,
                              const float* __restrict__ bias,
                              float* __restrict__ out)
{
    const int lane = threadIdx.x & 31;
    const int warp = threadIdx.x >> 5;
    const int gw = blockIdx.x*8 + warp;
    if (gw >= NB*10) return;
    const int n = gw / 10, o = gw % 10;

    float acc[16];
#pragma unroll
    for (int t = 0; t < 16; t++) acc[t] = 0.f;

    for (int f = lane; f < 128; f += 32) {
        const float4* av = reinterpret_cast<const float4*>(h8 + ((size_t)n*128 + f)*T);
        float wv = wt[o*128 + f];
        float4 a0 = av[0], a1 = av[1], a2 = av[2], a3 = av[3];
        acc[0] +=wv*a0.x; acc[1] +=wv*a0.y; acc[2] +=wv*a0.z; acc[3] +=wv*a0.w;
        acc[4] +=wv*a1.x; acc[5] +=wv*a1.y; acc[6] +=wv*a1.z; acc[7] +=wv*a1.w;
        acc[8] +=wv*a2.x; acc[9] +=wv*a2.y; acc[10]+=wv*a2.z; acc[11]+=wv*a2.w;
        acc[12]+=wv*a3.x; acc[13]+=wv*a3.y; acc[14]+=wv*a3.z; acc[15]+=wv*a3.w;
    }
#pragma unroll
    for (int t = 0; t < 16; t++)
#pragma unroll
        for (int off = 16; off; off >>= 1)
            acc[t] += __shfl_xor_sync(0xffffffffu, acc[t], off);

    if (lane == 0) {
        float b = bias[o];
        float u = 0.f, ssum = 0.f;
#pragma unroll
        for (int t = 0; t < 16; t++) {
            u += acc[t] + b;
            float sp = (u >= 1.0f) ? 1.0f : 0.0f;
            ssum += sp; u -= sp;
        }
        out[n*10 + o] = ssum * (1.0f/16.0f);
    }
}

// ---------------------------------------------------------------------
static inline int conv_smem(int cin, int cout, int ks, int pix, int cch) {
    int ckk  = cin*ks*ks;
    int wpad = (ckk*(cout+1) + 3) & ~3;
    return (wpad + cch*ks*(pix+ks-1)*T) * (int)sizeof(float);
}

extern "C" void kernel_launch(void* const* d_in, const int* /*in_sizes*/, int /*n_in*/,
                              void* d_out, int /*out_size*/)
{
    const float* x   = (const float*)d_in[0];
    const float* w1  = (const float*)d_in[1];
    const float* b1  = (const float*)d_in[2];
    const float* w2  = (const float*)d_in[3];
    const float* b2  = (const float*)d_in[4];
    const float* w3  = (const float*)d_in[5];
    const float* b3  = (const float*)d_in[6];
    const float* w4  = (const float*)d_in[7];
    const float* b4  = (const float*)d_in[8];
    const float* w5  = (const float*)d_in[9];
    const float* b5  = (const float*)d_in[10];
    const float* w6  = (const float*)d_in[11];
    const float* b6  = (const float*)d_in[12];
    const float* wf1 = (const float*)d_in[13];
    const float* bf1 = (const float*)d_in[14];
    const float* wf2 = (const float*)d_in[15];
    const float* bf2 = (const float*)d_in[16];
    float* out = (float*)d_out;

    float *h1,*h2,*h4,*h5,*h6,*h7,*h8,*dm;
    cudaGetSymbolAddress((void**)&h1, g_h1);
    cudaGetSymbolAddress((void**)&h2, g_h2);
    cudaGetSymbolAddress((void**)&h4, g_h4);
    cudaGetSymbolAddress((void**)&h5, g_h5);
    cudaGetSymbolAddress((void**)&h6, g_h6);
    cudaGetSymbolAddress((void**)&h7, g_h7);
    cudaGetSymbolAddress((void**)&h8, g_h8);
    cudaGetSymbolAddress((void**)&dm, g_dummy);

    // pipelined conv2/3 smem: weights 9504 + 3x5760 floats = 107136 B
    const int smP = (9504 + 3*5760) * (int)sizeof(float);
    cudaFuncSetAttribute((const void*)conv33_pipe_kernel<false,false>,
                         cudaFuncAttributeMaxDynamicSharedMemorySize, smP);
    cudaFuncSetAttribute((const void*)conv33_pipe_kernel<true,true>,
                         cudaFuncAttributeMaxDynamicSharedMemorySize, smP);

    const int sm1 = conv_smem(1,32,3,14,1);
    const int sm4 = conv_smem(32,16,1,14,8);
    const int sm5 = conv_smem(16,16,3,14,8);
    const int sm6 = conv_smem(16,32,1,14,16);

    // --- two no-op launches: keep ncu's capture slot on conv2 ---
    dummy_kernel<<<1, 32>>>(dm);
    dummy_kernel<<<1, 32>>>(dm);

    // L1: conv 1->32 3x3 pad1 + spike (RB=2 -> 3584 blocks)
    conv_spike_kernel<1,32,28,28,3,1,14,1,2,false>
        <<<dim3(2,14,NB), 32*14, sm1>>>(x, w1, b1, nullptr, h1);
    // L2: conv 32->32 3x3 pad1 + spike (round-7 pipelined, 4 px/thread)
    conv33_pipe_kernel<false,false>
        <<<dim3(1,7,NB), 224, smP>>>(h1, w2, b2, nullptr, h2);
    // L3: conv 32->32 3x3 pad1 + residual(h1) + spike + FUSED 2x2 pool
    //     + pool-LIF  -> writes pooled spikes h4 [N,32,14,14,T] directly
    conv33_pipe_kernel<true,true>
        <<<dim3(1,7,NB), 224, smP>>>(h2, w3, b3, h1, h4);
    // L4: conv 32->16 1x1 + spike (RB=1 -> 1792 blocks)
    conv_spike_kernel<32,16,14,14,1,0,14,8,1,false>
        <<<dim3(1,14,NB), 224, sm4>>>(h4, w4, b4, nullptr, h5);
    // L5: conv 16->16 3x3 pad1 + spike (RB=1 -> 1792 blocks)
    conv_spike_kernel<16,16,14,14,3,1,14,8,1,false>
        <<<dim3(1,14,NB), 224, sm5>>>(h5, w5, b5, nullptr, h6);
    // L6: conv 16->32 1x1 + residual(h4) + spike (RB=1 -> 1792 blocks)
    conv_spike_kernel<16,32,14,14,1,0,14,16,1,true>
        <<<dim3(1,14,NB), 448, sm6>>>(h6, w6, b6, h4, h7);
    // dense1 6272->128 + spike
    dense1_kernel<<<dim3(4,NB), 256>>>(h7, wf1, bf1, h8);
    // dense2 128->10 + spike + rate
    dense2_kernel<<<(NB*10 + 7)/8, 256>>>(h8, wf2, bf2, out);
}